// round 3
// baseline (speedup 1.0000x reference)
#include <cuda_runtime.h>
#include <cuda_bf16.h>
#include <math.h>

#define Bc 4
#define Nc 512
#define Cc 64
#define Hc 8
#define Fc 8

typedef unsigned int u32;

// ---------------- scratch (device globals: no allocs allowed) ----------------
__device__ float ssrc_g[Bc * Hc * Nc];             // (b,h,n)
__device__ float sdst_g[Bc * Hc * Nc];             // (b,h,n)
__device__ float xpT_g[Bc * Hc * Fc * Nc];         // projected nodes transposed [b][h][f][q]
__device__ float SE_g[(size_t)Bc * Hc * Nc * Nc];  // edge scores [b][h][p=j][q=i]
// B fragments pre-paired for direct per-thread LDG.64:
// layout [kk<4][tg<4][n<64][s<2], s=0 -> k2 = kk*8+tg, s=1 -> k2+4
// value = bf16x2 pair (We[2*k2][n], We[2*k2+1][n])
__device__ u32 Bfh_g[4 * 4 * 64 * 2];
__device__ u32 Bfl_g[4 * 4 * 64 * 2];

__device__ __forceinline__ void split2(float2 v, u32& hi, u32& lo) {
    __nv_bfloat16 h0 = __float2bfloat16_rn(v.x), h1 = __float2bfloat16_rn(v.y);
    __nv_bfloat16 l0 = __float2bfloat16_rn(v.x - __bfloat162float(h0));
    __nv_bfloat16 l1 = __float2bfloat16_rn(v.y - __bfloat162float(h1));
    __nv_bfloat162 ph = __halves2bfloat162(h0, h1);
    __nv_bfloat162 pl = __halves2bfloat162(l0, l1);
    hi = *(u32*)&ph;
    lo = *(u32*)&pl;
}

// ---------------- kernel 0: build split-bf16 B fragments ----------------
__global__ void k_wprep(const float* __restrict__ We) {
    int idx = blockIdx.x * 256 + threadIdx.x;      // 0..2047
    int s = idx & 1, n = (idx >> 1) & 63, tg = (idx >> 7) & 3, kk = idx >> 9;
    int k2 = kk * 8 + tg + 4 * s;
    float2 w = make_float2(We[(2 * k2) * 64 + n], We[(2 * k2 + 1) * 64 + n]);
    u32 hi, lo;
    split2(w, hi, lo);
    Bfh_g[idx] = hi;
    Bfl_g[idx] = lo;
}

// ---------------- kernel 1: xp = x@W (transposed out), s_src, s_dst ----------------
__global__ void k_proj(const float* __restrict__ x, const float* __restrict__ W,
                       const float* __restrict__ a_src, const float* __restrict__ a_dst) {
    __shared__ float xs[64];
    __shared__ float xps[64];
    int row = blockIdx.x;                          // b*512 + n
    int t = threadIdx.x;                           // 64 threads
    xs[t] = x[row * 64 + t];
    __syncthreads();
    float acc = 0.f;
#pragma unroll
    for (int c = 0; c < 64; c++) acc = fmaf(xs[c], W[c * 64 + t], acc);
    xps[t] = acc;
    int b = row >> 9, n = row & 511;
    xpT_g[(b * 64 + t) * 512 + n] = acc;           // t = h*8+f
    __syncthreads();
    if (t < 8) {
        float ss = 0.f, sd = 0.f;
#pragma unroll
        for (int f = 0; f < 8; f++) {
            float v = xps[t * 8 + f];
            ss = fmaf(v, a_src[t * 8 + f], ss);
            sd = fmaf(v, a_dst[t * 8 + f], sd);
        }
        ssrc_g[(b * 8 + t) * 512 + n] = ss;
        sdst_g[(b * 8 + t) * 512 + n] = sd;
    }
}

// ---------------- kernel 2: ep = e@We via register-direct bf16-split HMMA ----------------
// Block: 256 threads (8 warps). Tile: fixed j, 64 consecutive i rows, all 64 cols.
// Warp (wm<2, wn<4): M-range wm*32..+31 (mi<2 -> 16-row halves), N-range wn*16..+15.
// A fragments are loaded straight from e (coalesced 32B quad runs) and split to bf16
// hi/lo in registers; B fragments come from the tiny L1-resident prepped layout.
// No smem in the mainloop at all.
__global__ void __launch_bounds__(256, 2) k_edge(
    const float* __restrict__ e, const float* __restrict__ a_edge,
    float* __restrict__ e_out) {
    __shared__ float SCs[8 * 64];

    int t = threadIdx.x;
    int i0 = blockIdx.x * 64;
    int j = blockIdx.y;
    int b = blockIdx.z;

    int w = t >> 5, lane = t & 31;
    int wm = w & 1, wn = w >> 1;
    int g = lane >> 2, tg = lane & 3;

    // B fragments (L1-hot after first block on each SM)
    uint2 BH[4][2], BL[4][2];                      // [kk][ni]
#pragma unroll
    for (int kk = 0; kk < 4; kk++)
#pragma unroll
        for (int ni = 0; ni < 2; ni++) {
            int n = wn * 16 + ni * 8 + g;
            int off = (kk * 4 + tg) * 64 + n;
            BH[kk][ni] = ((const uint2*)Bfh_g)[off];
            BL[kk][ni] = ((const uint2*)Bfl_g)[off];
        }

    // e row pointers for this thread's fragment rows
    const float* rA[2];
#pragma unroll
    for (int mi = 0; mi < 2; mi++) {
        int r = i0 + wm * 32 + mi * 16 + g;
        rA[mi] = e + ((size_t)((b * 512 + r) * 512 + j)) * 64;
    }
    const size_t ROW8 = (size_t)8 * 512 * 64;      // +8 i-rows

    float c[2][2][4];
#pragma unroll
    for (int mi = 0; mi < 2; mi++)
#pragma unroll
        for (int ni = 0; ni < 2; ni++)
#pragma unroll
            for (int q = 0; q < 4; q++) c[mi][ni][q] = 0.f;

#pragma unroll
    for (int kk = 0; kk < 4; kk++) {
#pragma unroll
        for (int mi = 0; mi < 2; mi++) {
            int col = kk * 16 + 2 * tg;
            float2 e0 = *(const float2*)(rA[mi] + col);          // row g,   k
            float2 e1 = *(const float2*)(rA[mi] + ROW8 + col);   // row g+8, k
            float2 e2 = *(const float2*)(rA[mi] + col + 8);      // row g,   k+8
            float2 e3 = *(const float2*)(rA[mi] + ROW8 + col + 8);
            u32 ah0, ah1, ah2, ah3, al0, al1, al2, al3;
            split2(e0, ah0, al0);
            split2(e1, ah1, al1);
            split2(e2, ah2, al2);
            split2(e3, ah3, al3);
#pragma unroll
            for (int ni = 0; ni < 2; ni++) {
                float* cc = c[mi][ni];
                u32 bh0 = BH[kk][ni].x, bh1 = BH[kk][ni].y;
                u32 bl0 = BL[kk][ni].x, bl1 = BL[kk][ni].y;
#define MMA(A0,A1,A2,A3,B0,B1) \
    asm volatile("mma.sync.aligned.m16n8k16.row.col.f32.bf16.bf16.f32 " \
        "{%0,%1,%2,%3}, {%4,%5,%6,%7}, {%8,%9}, {%0,%1,%2,%3};" \
        : "+f"(cc[0]), "+f"(cc[1]), "+f"(cc[2]), "+f"(cc[3]) \
        : "r"(A0), "r"(A1), "r"(A2), "r"(A3), "r"(B0), "r"(B1))
                MMA(ah0, ah1, ah2, ah3, bh0, bh1);   // eh * Wh
                MMA(al0, al1, al2, al3, bh0, bh1);   // el * Wh
                MMA(ah0, ah1, ah2, ah3, bl0, bl1);   // eh * Wl
#undef MMA
            }
        }
    }

    // epilogue: elu -> e_out; head-dot partials -> SCs -> coalesced SE write
#pragma unroll
    for (int mi = 0; mi < 2; mi++) {
#pragma unroll
        for (int ni = 0; ni < 2; ni++) {
            int h = wn * 2 + ni;
            float ae0 = a_edge[h * 8 + 2 * tg];
            float ae1 = a_edge[h * 8 + 2 * tg + 1];
            float c0 = c[mi][ni][0], c1 = c[mi][ni][1];
            float c2 = c[mi][ni][2], c3 = c[mi][ni][3];
            int rAi = wm * 32 + mi * 16 + g, rBi = rAi + 8;
            size_t mA = (size_t)((b * 512 + i0 + rAi) * 512 + j);
            size_t mB = (size_t)((b * 512 + i0 + rBi) * 512 + j);
            float2 oA, oB;
            oA.x = (c0 > 0.f) ? c0 : expm1f(c0);
            oA.y = (c1 > 0.f) ? c1 : expm1f(c1);
            oB.x = (c2 > 0.f) ? c2 : expm1f(c2);
            oB.y = (c3 > 0.f) ? c3 : expm1f(c3);
            *(float2*)&e_out[mA * 64 + h * 8 + 2 * tg] = oA;
            *(float2*)&e_out[mB * 64 + h * 8 + 2 * tg] = oB;
            float pA = c0 * ae0 + c1 * ae1;
            float pB = c2 * ae0 + c3 * ae1;
            pA += __shfl_xor_sync(0xffffffffu, pA, 1);
            pA += __shfl_xor_sync(0xffffffffu, pA, 2);
            pB += __shfl_xor_sync(0xffffffffu, pB, 1);
            pB += __shfl_xor_sync(0xffffffffu, pB, 2);
            if (tg == 0) {
                SCs[h * 64 + rAi] = pA;
                SCs[h * 64 + rBi] = pB;
            }
        }
    }
    __syncthreads();
    {
        int idx = t * 2;                           // 512 floats
        int h = idx >> 6, q = idx & 63;
        float2 v = *(float2*)&SCs[idx];
        size_t o = ((size_t)((b * 8 + h) * 512 + j)) * 512 + (size_t)(i0 + q);
        *(float2*)&SE_g[o] = v;                    // SE[b][h][p=j][q=i], coalesced
    }
}

// ---------------- kernel 3: masked softmax + att@xp + residual + elu ----------------
__global__ void __launch_bounds__(256) k_attn(
    const float* __restrict__ adj, const float* __restrict__ x,
    const float* __restrict__ bias, float* __restrict__ out) {
    int bp = blockIdx.x;
    int b = bp >> 9, p = bp & 511;
    int h = threadIdx.x >> 5, lane = threadIdx.x & 31;

    const float* SErow = SE_g + ((size_t)((b * 8 + h) * 512 + p)) * 512;
    const float* adjrow = adj + (size_t)(b * 512 + p) * 512;
    const float* sd = sdst_g + (b * 8 + h) * 512;
    float ssrc = ssrc_g[(b * 8 + h) * 512 + p];

    float4 sc[4];
    float mx = -3.0e38f;
#pragma unroll
    for (int tt = 0; tt < 4; tt++) {
        int q = 4 * lane + 128 * tt;
        float4 a = *(const float4*)&adjrow[q];
        float4 se = *(const float4*)&SErow[q];
        float4 sv = *(const float4*)&sd[q];
        float s0 = ssrc + sv.x + se.x; s0 = (s0 > 0.f) ? s0 : 0.2f * s0; s0 = (a.x < 0.5f) ? -3.0e38f : s0;
        float s1 = ssrc + sv.y + se.y; s1 = (s1 > 0.f) ? s1 : 0.2f * s1; s1 = (a.y < 0.5f) ? -3.0e38f : s1;
        float s2 = ssrc + sv.z + se.z; s2 = (s2 > 0.f) ? s2 : 0.2f * s2; s2 = (a.z < 0.5f) ? -3.0e38f : s2;
        float s3 = ssrc + sv.w + se.w; s3 = (s3 > 0.f) ? s3 : 0.2f * s3; s3 = (a.w < 0.5f) ? -3.0e38f : s3;
        sc[tt] = make_float4(s0, s1, s2, s3);
        mx = fmaxf(mx, fmaxf(fmaxf(s0, s1), fmaxf(s2, s3)));
    }
#pragma unroll
    for (int o = 16; o; o >>= 1) mx = fmaxf(mx, __shfl_xor_sync(0xffffffffu, mx, o));

    float sum = 0.f;
#pragma unroll
    for (int tt = 0; tt < 4; tt++) {
        float4 s = sc[tt];
        s.x = (s.x < -1.0e38f) ? 0.f : __expf(s.x - mx);
        s.y = (s.y < -1.0e38f) ? 0.f : __expf(s.y - mx);
        s.z = (s.z < -1.0e38f) ? 0.f : __expf(s.z - mx);
        s.w = (s.w < -1.0e38f) ? 0.f : __expf(s.w - mx);
        sc[tt] = s;
        sum += s.x + s.y + s.z + s.w;
    }
#pragma unroll
    for (int o = 16; o; o >>= 1) sum += __shfl_xor_sync(0xffffffffu, sum, o);

    const float* xpT = xpT_g + (size_t)(b * 64 + h * 8) * 512;
    float oa[8] = {0.f, 0.f, 0.f, 0.f, 0.f, 0.f, 0.f, 0.f};
#pragma unroll
    for (int tt = 0; tt < 4; tt++) {
        int q = 4 * lane + 128 * tt;
        float4 s = sc[tt];
#pragma unroll
        for (int f = 0; f < 8; f++) {
            float4 xv = *(const float4*)&xpT[f * 512 + q];   // coalesced over q
            oa[f] += s.x * xv.x + s.y * xv.y + s.z * xv.z + s.w * xv.w;
        }
    }
#pragma unroll
    for (int o = 16; o; o >>= 1) {
#pragma unroll
        for (int f = 0; f < 8; f++) oa[f] += __shfl_xor_sync(0xffffffffu, oa[f], o);
    }

    __shared__ float os[64];
    if (lane == 0) {
        float inv = 1.f / sum;
#pragma unroll
        for (int f = 0; f < 8; f++) {
            float v = oa[f] * inv + x[(size_t)(b * 512 + p) * 64 + h * 8 + f] + bias[h * 8 + f];
            os[h * 8 + f] = (v > 0.f) ? v : expm1f(v);
        }
    }
    __syncthreads();
    if (threadIdx.x < 16)
        ((float4*)(out + (size_t)(b * 512 + p) * 64))[threadIdx.x] =
            ((const float4*)os)[threadIdx.x];
}

// ---------------- launch ----------------
extern "C" void kernel_launch(void* const* d_in, const int* in_sizes, int n_in,
                              void* d_out, int out_size) {
    const float* adj    = (const float*)d_in[0];
    const float* x      = (const float*)d_in[1];
    const float* e      = (const float*)d_in[2];
    const float* W      = (const float*)d_in[3];
    const float* We     = (const float*)d_in[4];
    const float* a_src  = (const float*)d_in[5];
    const float* a_dst  = (const float*)d_in[6];
    const float* a_edge = (const float*)d_in[7];
    const float* bias   = (const float*)d_in[8];

    float* out = (float*)d_out;
    float* e_out = out + Bc * Nc * Cc;   // out first, then e_out

    k_wprep<<<8, 256>>>(We);
    k_proj<<<Bc * Nc, 64>>>(x, W, a_src, a_dst);
    k_edge<<<dim3(Nc / 64, Nc, Bc), 256>>>(e, a_edge, e_out);
    k_attn<<<Bc * Nc, 256>>>(adj, x, bias, out);
}

// round 4
// speedup vs baseline: 1.6019x; 1.6019x over previous
#include <cuda_runtime.h>
#include <cuda_bf16.h>
#include <math.h>

#define Bc 4
#define Nc 512
#define Cc 64
#define Hc 8
#define Fc 8

typedef unsigned int u32;

// ---------------- scratch (device globals: no allocs allowed) ----------------
__device__ float ssrc_g[Bc * Hc * Nc];             // (b,h,n)
__device__ float sdst_g[Bc * Hc * Nc];             // (b,h,n)
__device__ float xpT_g[Bc * Hc * Fc * Nc];         // projected nodes transposed [b][h][f][q]
__device__ float SE_g[(size_t)Bc * Hc * Nc * Nc];  // edge scores [b][h][p=j][q=i]
// B fragments pre-paired for direct per-thread LDG.64 (L1-resident, 16KB total):
// layout [kk<4][tg<4][n<64][s<2], s=0 -> k2 = kk*8+tg, s=1 -> k2+4
// value = bf16x2 pair (We[2*k2][n], We[2*k2+1][n])
__device__ u32 Bfh_g[4 * 4 * 64 * 2];
__device__ u32 Bfl_g[4 * 4 * 64 * 2];

__device__ __forceinline__ void split2(float2 v, u32& hi, u32& lo) {
    __nv_bfloat16 h0 = __float2bfloat16_rn(v.x), h1 = __float2bfloat16_rn(v.y);
    __nv_bfloat16 l0 = __float2bfloat16_rn(v.x - __bfloat162float(h0));
    __nv_bfloat16 l1 = __float2bfloat16_rn(v.y - __bfloat162float(h1));
    __nv_bfloat162 ph = __halves2bfloat162(h0, h1);
    __nv_bfloat162 pl = __halves2bfloat162(l0, l1);
    hi = *(u32*)&ph;
    lo = *(u32*)&pl;
}

// ---------------- kernel 0: build split-bf16 B fragments ----------------
__global__ void k_wprep(const float* __restrict__ We) {
    int idx = blockIdx.x * 256 + threadIdx.x;      // 0..2047
    int s = idx & 1, n = (idx >> 1) & 63, tg = (idx >> 7) & 3, kk = idx >> 9;
    int k2 = kk * 8 + tg + 4 * s;
    float2 w = make_float2(We[(2 * k2) * 64 + n], We[(2 * k2 + 1) * 64 + n]);
    u32 hi, lo;
    split2(w, hi, lo);
    Bfh_g[idx] = hi;
    Bfl_g[idx] = lo;
}

// ---------------- kernel 1: xp = x@W (transposed out), s_src, s_dst ----------------
__global__ void k_proj(const float* __restrict__ x, const float* __restrict__ W,
                       const float* __restrict__ a_src, const float* __restrict__ a_dst) {
    __shared__ float xs[64];
    __shared__ float xps[64];
    int row = blockIdx.x;                          // b*512 + n
    int t = threadIdx.x;                           // 64 threads
    xs[t] = x[row * 64 + t];
    __syncthreads();
    float acc = 0.f;
#pragma unroll
    for (int c = 0; c < 64; c++) acc = fmaf(xs[c], W[c * 64 + t], acc);
    xps[t] = acc;
    int b = row >> 9, n = row & 511;
    xpT_g[(b * 64 + t) * 512 + n] = acc;           // t = h*8+f
    __syncthreads();
    if (t < 8) {
        float ss = 0.f, sd = 0.f;
#pragma unroll
        for (int f = 0; f < 8; f++) {
            float v = xps[t * 8 + f];
            ss = fmaf(v, a_src[t * 8 + f], ss);
            sd = fmaf(v, a_dst[t * 8 + f], sd);
        }
        ssrc_g[(b * 8 + t) * 512 + n] = ss;
        sdst_g[(b * 8 + t) * 512 + n] = sd;
    }
}

// ---------------- kernel 2: ep = e@We via bf16-split HMMA ----------------
// Block: 128 threads (4 warps). Tile: fixed j, 32 consecutive i rows, all 64 cols.
// A staged through smem (coalesced float4 LDG, conflict-free LDS); B fragments
// loaded directly from the prepped global layout (L1-hot). Warp wn<4 owns N-range
// wn*16..+15 (heads wn*2+{0,1}); all warps cover the full 32 M-rows (mi<2).
#define APAD 72   // halves per A row (64 data + 8 pad)

__global__ void __launch_bounds__(128, 6) k_edge(
    const float* __restrict__ e, const float* __restrict__ a_edge,
    float* __restrict__ e_out) {
    __shared__ __align__(16) __nv_bfloat16 Ah[32 * APAD];
    __shared__ __align__(16) __nv_bfloat16 Al[32 * APAD];
    __shared__ float SCs[8 * 32];

    int t = threadIdx.x;
    int i0 = blockIdx.x * 32;
    int j = blockIdx.y;
    int b = blockIdx.z;

    int wn = t >> 5, lane = t & 31;
    int g = lane >> 2, tg = lane & 3;

    // B fragments direct from global (tiny; L1-hot after first block per SM)
    uint2 BH[4][2], BL[4][2];                      // [kk][ni]
#pragma unroll
    for (int kk = 0; kk < 4; kk++)
#pragma unroll
        for (int ni = 0; ni < 2; ni++) {
            int n = wn * 16 + ni * 8 + g;
            int off = (kk * 4 + tg) * 64 + n;
            BH[kk][ni] = ((const uint2*)Bfh_g)[off];
            BL[kk][ni] = ((const uint2*)Bfl_g)[off];
        }

    // stage e tile: 32 rows x 64 f32 (8KB), convert to bf16 hi/lo
    {
        const float4* eg4 = (const float4*)e;
#pragma unroll
        for (int u = 0; u < 4; u++) {
            int F = t + 128 * u;                   // 512 float4
            int r = F >> 4, c4 = F & 15;
            size_t grow = (size_t)((b * 512 + i0 + r) * 512 + j);
            float4 v = eg4[grow * 16 + c4];
            u32 h01, l01, h23, l23;
            split2(make_float2(v.x, v.y), h01, l01);
            split2(make_float2(v.z, v.w), h23, l23);
            *(uint2*)&Ah[r * APAD + c4 * 4] = make_uint2(h01, h23);
            *(uint2*)&Al[r * APAD + c4 * 4] = make_uint2(l01, l23);
        }
    }
    __syncthreads();

    float c[2][2][4];
#pragma unroll
    for (int mi = 0; mi < 2; mi++)
#pragma unroll
        for (int ni = 0; ni < 2; ni++)
#pragma unroll
            for (int q = 0; q < 4; q++) c[mi][ni][q] = 0.f;

#pragma unroll
    for (int kk = 0; kk < 4; kk++) {
#pragma unroll
        for (int mi = 0; mi < 2; mi++) {
            int baseA = (mi * 16 + g) * APAD + kk * 16 + 2 * tg;
            int baseB = (mi * 16 + g + 8) * APAD + kk * 16 + 2 * tg;
            u32 ah0 = *(u32*)&Ah[baseA];
            u32 ah1 = *(u32*)&Ah[baseB];
            u32 ah2 = *(u32*)&Ah[baseA + 8];
            u32 ah3 = *(u32*)&Ah[baseB + 8];
            u32 al0 = *(u32*)&Al[baseA];
            u32 al1 = *(u32*)&Al[baseB];
            u32 al2 = *(u32*)&Al[baseA + 8];
            u32 al3 = *(u32*)&Al[baseB + 8];
#pragma unroll
            for (int ni = 0; ni < 2; ni++) {
                float* cc = c[mi][ni];
                u32 bh0 = BH[kk][ni].x, bh1 = BH[kk][ni].y;
                u32 bl0 = BL[kk][ni].x, bl1 = BL[kk][ni].y;
#define MMA(A0,A1,A2,A3,B0,B1) \
    asm volatile("mma.sync.aligned.m16n8k16.row.col.f32.bf16.bf16.f32 " \
        "{%0,%1,%2,%3}, {%4,%5,%6,%7}, {%8,%9}, {%0,%1,%2,%3};" \
        : "+f"(cc[0]), "+f"(cc[1]), "+f"(cc[2]), "+f"(cc[3]) \
        : "r"(A0), "r"(A1), "r"(A2), "r"(A3), "r"(B0), "r"(B1))
                MMA(ah0, ah1, ah2, ah3, bh0, bh1);   // eh * Wh
                MMA(al0, al1, al2, al3, bh0, bh1);   // el * Wh
                MMA(ah0, ah1, ah2, ah3, bl0, bl1);   // eh * Wl
#undef MMA
            }
        }
    }

    // epilogue: elu -> e_out; head-dot partials -> SCs -> coalesced SE write
#pragma unroll
    for (int mi = 0; mi < 2; mi++) {
#pragma unroll
        for (int ni = 0; ni < 2; ni++) {
            int h = wn * 2 + ni;
            float ae0 = a_edge[h * 8 + 2 * tg];
            float ae1 = a_edge[h * 8 + 2 * tg + 1];
            float c0 = c[mi][ni][0], c1 = c[mi][ni][1];
            float c2 = c[mi][ni][2], c3 = c[mi][ni][3];
            int rAi = mi * 16 + g, rBi = rAi + 8;
            size_t mA = (size_t)((b * 512 + i0 + rAi) * 512 + j);
            size_t mB = (size_t)((b * 512 + i0 + rBi) * 512 + j);
            float2 oA, oB;
            oA.x = (c0 > 0.f) ? c0 : expm1f(c0);
            oA.y = (c1 > 0.f) ? c1 : expm1f(c1);
            oB.x = (c2 > 0.f) ? c2 : expm1f(c2);
            oB.y = (c3 > 0.f) ? c3 : expm1f(c3);
            *(float2*)&e_out[mA * 64 + h * 8 + 2 * tg] = oA;
            *(float2*)&e_out[mB * 64 + h * 8 + 2 * tg] = oB;
            float pA = c0 * ae0 + c1 * ae1;
            float pB = c2 * ae0 + c3 * ae1;
            pA += __shfl_xor_sync(0xffffffffu, pA, 1);
            pA += __shfl_xor_sync(0xffffffffu, pA, 2);
            pB += __shfl_xor_sync(0xffffffffu, pB, 1);
            pB += __shfl_xor_sync(0xffffffffu, pB, 2);
            if (tg == 0) {
                SCs[h * 32 + rAi] = pA;
                SCs[h * 32 + rBi] = pB;
            }
        }
    }
    __syncthreads();
    {
        int idx = t * 2;                           // 256 floats: [h<8][q<32]
        int h = idx >> 5, q = idx & 31;
        float2 v = *(float2*)&SCs[idx];
        size_t o = ((size_t)((b * 8 + h) * 512 + j)) * 512 + (size_t)(i0 + q);
        *(float2*)&SE_g[o] = v;                    // SE[b][h][p=j][q=i]
    }
}

// ---------------- kernel 3: masked softmax + att@xp + residual + elu ----------------
__global__ void __launch_bounds__(256) k_attn(
    const float* __restrict__ adj, const float* __restrict__ x,
    const float* __restrict__ bias, float* __restrict__ out) {
    int bp = blockIdx.x;
    int b = bp >> 9, p = bp & 511;
    int h = threadIdx.x >> 5, lane = threadIdx.x & 31;

    const float* SErow = SE_g + ((size_t)((b * 8 + h) * 512 + p)) * 512;
    const float* adjrow = adj + (size_t)(b * 512 + p) * 512;
    const float* sd = sdst_g + (b * 8 + h) * 512;
    float ssrc = ssrc_g[(b * 8 + h) * 512 + p];

    float4 sc[4];
    float mx = -3.0e38f;
#pragma unroll
    for (int tt = 0; tt < 4; tt++) {
        int q = 4 * lane + 128 * tt;
        float4 a = *(const float4*)&adjrow[q];
        float4 se = *(const float4*)&SErow[q];
        float4 sv = *(const float4*)&sd[q];
        float s0 = ssrc + sv.x + se.x; s0 = (s0 > 0.f) ? s0 : 0.2f * s0; s0 = (a.x < 0.5f) ? -3.0e38f : s0;
        float s1 = ssrc + sv.y + se.y; s1 = (s1 > 0.f) ? s1 : 0.2f * s1; s1 = (a.y < 0.5f) ? -3.0e38f : s1;
        float s2 = ssrc + sv.z + se.z; s2 = (s2 > 0.f) ? s2 : 0.2f * s2; s2 = (a.z < 0.5f) ? -3.0e38f : s2;
        float s3 = ssrc + sv.w + se.w; s3 = (s3 > 0.f) ? s3 : 0.2f * s3; s3 = (a.w < 0.5f) ? -3.0e38f : s3;
        sc[tt] = make_float4(s0, s1, s2, s3);
        mx = fmaxf(mx, fmaxf(fmaxf(s0, s1), fmaxf(s2, s3)));
    }
#pragma unroll
    for (int o = 16; o; o >>= 1) mx = fmaxf(mx, __shfl_xor_sync(0xffffffffu, mx, o));

    float sum = 0.f;
#pragma unroll
    for (int tt = 0; tt < 4; tt++) {
        float4 s = sc[tt];
        s.x = (s.x < -1.0e38f) ? 0.f : __expf(s.x - mx);
        s.y = (s.y < -1.0e38f) ? 0.f : __expf(s.y - mx);
        s.z = (s.z < -1.0e38f) ? 0.f : __expf(s.z - mx);
        s.w = (s.w < -1.0e38f) ? 0.f : __expf(s.w - mx);
        sc[tt] = s;
        sum += s.x + s.y + s.z + s.w;
    }
#pragma unroll
    for (int o = 16; o; o >>= 1) sum += __shfl_xor_sync(0xffffffffu, sum, o);

    const float* xpT = xpT_g + (size_t)(b * 64 + h * 8) * 512;
    float oa[8] = {0.f, 0.f, 0.f, 0.f, 0.f, 0.f, 0.f, 0.f};
#pragma unroll
    for (int tt = 0; tt < 4; tt++) {
        int q = 4 * lane + 128 * tt;
        float4 s = sc[tt];
#pragma unroll
        for (int f = 0; f < 8; f++) {
            float4 xv = *(const float4*)&xpT[f * 512 + q];   // coalesced over q
            oa[f] += s.x * xv.x + s.y * xv.y + s.z * xv.z + s.w * xv.w;
        }
    }
#pragma unroll
    for (int o = 16; o; o >>= 1) {
#pragma unroll
        for (int f = 0; f < 8; f++) oa[f] += __shfl_xor_sync(0xffffffffu, oa[f], o);
    }

    __shared__ float os[64];
    if (lane == 0) {
        float inv = 1.f / sum;
#pragma unroll
        for (int f = 0; f < 8; f++) {
            float v = oa[f] * inv + x[(size_t)(b * 512 + p) * 64 + h * 8 + f] + bias[h * 8 + f];
            os[h * 8 + f] = (v > 0.f) ? v : expm1f(v);
        }
    }
    __syncthreads();
    if (threadIdx.x < 16)
        ((float4*)(out + (size_t)(b * 512 + p) * 64))[threadIdx.x] =
            ((const float4*)os)[threadIdx.x];
}

// ---------------- launch ----------------
extern "C" void kernel_launch(void* const* d_in, const int* in_sizes, int n_in,
                              void* d_out, int out_size) {
    const float* adj    = (const float*)d_in[0];
    const float* x      = (const float*)d_in[1];
    const float* e      = (const float*)d_in[2];
    const float* W      = (const float*)d_in[3];
    const float* We     = (const float*)d_in[4];
    const float* a_src  = (const float*)d_in[5];
    const float* a_dst  = (const float*)d_in[6];
    const float* a_edge = (const float*)d_in[7];
    const float* bias   = (const float*)d_in[8];

    float* out = (float*)d_out;
    float* e_out = out + Bc * Nc * Cc;   // out first, then e_out

    k_wprep<<<8, 256>>>(We);
    k_proj<<<Bc * Nc, 64>>>(x, W, a_src, a_dst);
    k_edge<<<dim3(Nc / 32, Nc, Bc), 128>>>(e, a_edge, e_out);
    k_attn<<<Bc * Nc, 256>>>(adj, x, bias, out);
}

// round 5
// speedup vs baseline: 1.7956x; 1.1209x over previous
#include <cuda_runtime.h>
#include <cuda_bf16.h>
#include <math.h>

#define Bc 4
#define Nc 512
#define Cc 64
#define Hc 8
#define Fc 8

typedef unsigned int u32;

// ---------------- scratch (device globals: no allocs allowed) ----------------
__device__ float ssrc_g[Bc * Hc * Nc];             // (b,h,n)
__device__ float sdst_g[Bc * Hc * Nc];             // (b,h,n)
__device__ float xpT_g[Bc * Hc * Fc * Nc];         // projected nodes transposed [b][h][f][q]
__device__ float SE_g[(size_t)Bc * Hc * Nc * Nc];  // edge scores [b][h][p=j][q=i]
// B fragments pre-paired for direct per-thread LDG.64 (L1-resident, 16KB total):
// layout [kk<4][tg<4][n<64][s<2], s=0 -> k2 = kk*8+tg, s=1 -> k2+4
// value = bf16x2 pair (We[2*k2][n], We[2*k2+1][n])
__device__ u32 Bfh_g[4 * 4 * 64 * 2];
__device__ u32 Bfl_g[4 * 4 * 64 * 2];

__device__ __forceinline__ void split2(float2 v, u32& hi, u32& lo) {
    __nv_bfloat16 h0 = __float2bfloat16_rn(v.x), h1 = __float2bfloat16_rn(v.y);
    __nv_bfloat16 l0 = __float2bfloat16_rn(v.x - __bfloat162float(h0));
    __nv_bfloat16 l1 = __float2bfloat16_rn(v.y - __bfloat162float(h1));
    __nv_bfloat162 ph = __halves2bfloat162(h0, h1);
    __nv_bfloat162 pl = __halves2bfloat162(l0, l1);
    hi = *(u32*)&ph;
    lo = *(u32*)&pl;
}

// fast branchless elu: 5-term Taylor on (-0.25,0], __expf-1 below; identity above 0
__device__ __forceinline__ float elu1(float v) {
    float p = fmaf(v, 1.f / 120.f, 1.f / 24.f);
    p = fmaf(p, v, 1.f / 6.f);
    p = fmaf(p, v, 0.5f);
    p = fmaf(p, v, 1.f);
    p = p * v;
    float ex = __expf(v) - 1.f;
    float r = (v > -0.25f) ? p : ex;
    return (v > 0.f) ? v : r;
}

// ---------------- kernel 0: build split-bf16 B fragments ----------------
__global__ void k_wprep(const float* __restrict__ We) {
    int idx = blockIdx.x * 256 + threadIdx.x;      // 0..2047
    int s = idx & 1, n = (idx >> 1) & 63, tg = (idx >> 7) & 3, kk = idx >> 9;
    int k2 = kk * 8 + tg + 4 * s;
    float2 w = make_float2(We[(2 * k2) * 64 + n], We[(2 * k2 + 1) * 64 + n]);
    u32 hi, lo;
    split2(w, hi, lo);
    Bfh_g[idx] = hi;
    Bfl_g[idx] = lo;
}

// ---------------- kernel 1: xp = x@W (transposed out), s_src, s_dst ----------------
__global__ void k_proj(const float* __restrict__ x, const float* __restrict__ W,
                       const float* __restrict__ a_src, const float* __restrict__ a_dst) {
    __shared__ float xs[64];
    __shared__ float xps[64];
    int row = blockIdx.x;                          // b*512 + n
    int t = threadIdx.x;                           // 64 threads
    xs[t] = x[row * 64 + t];
    __syncthreads();
    float acc = 0.f;
#pragma unroll
    for (int c = 0; c < 64; c++) acc = fmaf(xs[c], W[c * 64 + t], acc);
    xps[t] = acc;
    int b = row >> 9, n = row & 511;
    xpT_g[(b * 64 + t) * 512 + n] = acc;           // t = h*8+f
    __syncthreads();
    if (t < 8) {
        float ss = 0.f, sd = 0.f;
#pragma unroll
        for (int f = 0; f < 8; f++) {
            float v = xps[t * 8 + f];
            ss = fmaf(v, a_src[t * 8 + f], ss);
            sd = fmaf(v, a_dst[t * 8 + f], sd);
        }
        ssrc_g[(b * 8 + t) * 512 + n] = ss;
        sdst_g[(b * 8 + t) * 512 + n] = sd;
    }
}

// ---------------- kernel 2: ep = e@We via bf16-split HMMA ----------------
// Block: 128 threads (4 warps, 2x2 M/N grid). Tile: fixed j, 64 i rows, 64 cols.
// Warp (wm, wn2): rows wm*32..+31 (mi<2), cols wn2*32..+31 (ni<4, heads wn2*4+ni).
// A staged in smem (bf16 hi/lo); B fragments from L1-hot prepped global layout.
// Epilogue routes ep through smem (union with A) for coalesced STG.128 e_out.
#define APAD 72   // halves per A row (64 data + 8 pad); also floats per Os row

__global__ void __launch_bounds__(128, 3) k_edge(
    const float* __restrict__ e, const float* __restrict__ a_edge,
    float* __restrict__ e_out) {
    __shared__ __align__(16) unsigned char U[64 * APAD * 4];  // Ah+Al  <->  Os
    __shared__ float SCs[8 * 64];
    __nv_bfloat16* Ah = (__nv_bfloat16*)U;
    __nv_bfloat16* Al = Ah + 64 * APAD;
    float* Os = (float*)U;

    int t = threadIdx.x;
    int i0 = blockIdx.x * 64;
    int j = blockIdx.y;
    int b = blockIdx.z;

    int w = t >> 5, lane = t & 31;
    int wm = w & 1, wn2 = w >> 1;
    int g = lane >> 2, tg = lane & 3;

    // B fragments direct from global (tiny; L1-hot after first block per SM)
    uint2 BH[4][4], BL[4][4];                      // [kk][ni]
#pragma unroll
    for (int kk = 0; kk < 4; kk++)
#pragma unroll
        for (int ni = 0; ni < 4; ni++) {
            int n = wn2 * 32 + ni * 8 + g;
            int off = (kk * 4 + tg) * 64 + n;
            BH[kk][ni] = ((const uint2*)Bfh_g)[off];
            BL[kk][ni] = ((const uint2*)Bfl_g)[off];
        }

    // stage e tile: 64 rows x 64 f32 (16KB), convert to bf16 hi/lo
    {
        const float4* eg4 = (const float4*)e;
#pragma unroll
        for (int u = 0; u < 8; u++) {
            int F = t + 128 * u;                   // 1024 float4
            int r = F >> 4, c4 = F & 15;
            size_t grow = (size_t)((b * 512 + i0 + r) * 512 + j);
            float4 v = eg4[grow * 16 + c4];
            u32 h01, l01, h23, l23;
            split2(make_float2(v.x, v.y), h01, l01);
            split2(make_float2(v.z, v.w), h23, l23);
            *(uint2*)&Ah[r * APAD + c4 * 4] = make_uint2(h01, h23);
            *(uint2*)&Al[r * APAD + c4 * 4] = make_uint2(l01, l23);
        }
    }
    __syncthreads();

    float c[2][4][4];
#pragma unroll
    for (int mi = 0; mi < 2; mi++)
#pragma unroll
        for (int ni = 0; ni < 4; ni++)
#pragma unroll
            for (int q = 0; q < 4; q++) c[mi][ni][q] = 0.f;

#pragma unroll
    for (int kk = 0; kk < 4; kk++) {
#pragma unroll
        for (int mi = 0; mi < 2; mi++) {
            int rbA = (wm * 32 + mi * 16 + g) * APAD + kk * 16 + 2 * tg;
            int rbB = (wm * 32 + mi * 16 + g + 8) * APAD + kk * 16 + 2 * tg;
            u32 ah0 = *(u32*)&Ah[rbA];
            u32 ah1 = *(u32*)&Ah[rbB];
            u32 ah2 = *(u32*)&Ah[rbA + 8];
            u32 ah3 = *(u32*)&Ah[rbB + 8];
            u32 al0 = *(u32*)&Al[rbA];
            u32 al1 = *(u32*)&Al[rbB];
            u32 al2 = *(u32*)&Al[rbA + 8];
            u32 al3 = *(u32*)&Al[rbB + 8];
#pragma unroll
            for (int ni = 0; ni < 4; ni++) {
                float* cc = c[mi][ni];
                u32 bh0 = BH[kk][ni].x, bh1 = BH[kk][ni].y;
                u32 bl0 = BL[kk][ni].x, bl1 = BL[kk][ni].y;
#define MMA(A0,A1,A2,A3,B0,B1) \
    asm volatile("mma.sync.aligned.m16n8k16.row.col.f32.bf16.bf16.f32 " \
        "{%0,%1,%2,%3}, {%4,%5,%6,%7}, {%8,%9}, {%0,%1,%2,%3};" \
        : "+f"(cc[0]), "+f"(cc[1]), "+f"(cc[2]), "+f"(cc[3]) \
        : "r"(A0), "r"(A1), "r"(A2), "r"(A3), "r"(B0), "r"(B1))
                MMA(ah0, ah1, ah2, ah3, bh0, bh1);   // eh * Wh
                MMA(al0, al1, al2, al3, bh0, bh1);   // el * Wh
                MMA(ah0, ah1, ah2, ah3, bl0, bl1);   // eh * Wl
#undef MMA
            }
        }
    }
    __syncthreads();   // all warps done reading Ah/Al before Os overwrites

    // epilogue: raw ep -> Os (smem); head-dot partials -> SCs
#pragma unroll
    for (int mi = 0; mi < 2; mi++) {
#pragma unroll
        for (int ni = 0; ni < 4; ni++) {
            int h = wn2 * 4 + ni;
            float ae0 = a_edge[h * 8 + 2 * tg];
            float ae1 = a_edge[h * 8 + 2 * tg + 1];
            float c0 = c[mi][ni][0], c1 = c[mi][ni][1];
            float c2 = c[mi][ni][2], c3 = c[mi][ni][3];
            int rAi = wm * 32 + mi * 16 + g, rBi = rAi + 8;
            int col = h * 8 + 2 * tg;
            *(float2*)&Os[rAi * APAD + col] = make_float2(c0, c1);
            *(float2*)&Os[rBi * APAD + col] = make_float2(c2, c3);
            float pA = c0 * ae0 + c1 * ae1;
            float pB = c2 * ae0 + c3 * ae1;
            pA += __shfl_xor_sync(0xffffffffu, pA, 1);
            pA += __shfl_xor_sync(0xffffffffu, pA, 2);
            pB += __shfl_xor_sync(0xffffffffu, pB, 1);
            pB += __shfl_xor_sync(0xffffffffu, pB, 2);
            if (tg == 0) {
                SCs[h * 64 + rAi] = pA;
                SCs[h * 64 + rBi] = pB;
            }
        }
    }
    __syncthreads();

    // coalesced stores: e_out (elu applied on the way out) + SE
    {
        float* eob = e_out + (size_t)((b * 512 + i0) * 512 + j) * 64;
#pragma unroll
        for (int u = 0; u < 8; u++) {
            int F = t + 128 * u;                   // 1024 float4
            int r = F >> 4, c4 = F & 15;
            float4 v = *(float4*)&Os[r * APAD + c4 * 4];
            v.x = elu1(v.x);
            v.y = elu1(v.y);
            v.z = elu1(v.z);
            v.w = elu1(v.w);
            *(float4*)&eob[(size_t)r * 512 * 64 + c4 * 4] = v;
        }
    }
    {
        int idx = t * 4;                           // 512 floats: [h<8][q<64]
        int h = idx >> 6, q = idx & 63;
        float4 v = *(float4*)&SCs[idx];
        size_t o = ((size_t)((b * 8 + h) * 512 + j)) * 512 + (size_t)(i0 + q);
        *(float4*)&SE_g[o] = v;                    // SE[b][h][p=j][q=i]
    }
}

// ---------------- kernel 3: masked softmax + att@xp + residual + elu ----------------
__global__ void __launch_bounds__(256) k_attn(
    const float* __restrict__ adj, const float* __restrict__ x,
    const float* __restrict__ bias, float* __restrict__ out) {
    int bp = blockIdx.x;
    int b = bp >> 9, p = bp & 511;
    int h = threadIdx.x >> 5, lane = threadIdx.x & 31;

    const float* SErow = SE_g + ((size_t)((b * 8 + h) * 512 + p)) * 512;
    const float* adjrow = adj + (size_t)(b * 512 + p) * 512;
    const float* sd = sdst_g + (b * 8 + h) * 512;
    float ssrc = ssrc_g[(b * 8 + h) * 512 + p];

    float4 sc[4];
    float mx = -3.0e38f;
#pragma unroll
    for (int tt = 0; tt < 4; tt++) {
        int q = 4 * lane + 128 * tt;
        float4 a = *(const float4*)&adjrow[q];
        float4 se = *(const float4*)&SErow[q];
        float4 sv = *(const float4*)&sd[q];
        float s0 = ssrc + sv.x + se.x; s0 = (s0 > 0.f) ? s0 : 0.2f * s0; s0 = (a.x < 0.5f) ? -3.0e38f : s0;
        float s1 = ssrc + sv.y + se.y; s1 = (s1 > 0.f) ? s1 : 0.2f * s1; s1 = (a.y < 0.5f) ? -3.0e38f : s1;
        float s2 = ssrc + sv.z + se.z; s2 = (s2 > 0.f) ? s2 : 0.2f * s2; s2 = (a.z < 0.5f) ? -3.0e38f : s2;
        float s3 = ssrc + sv.w + se.w; s3 = (s3 > 0.f) ? s3 : 0.2f * s3; s3 = (a.w < 0.5f) ? -3.0e38f : s3;
        sc[tt] = make_float4(s0, s1, s2, s3);
        mx = fmaxf(mx, fmaxf(fmaxf(s0, s1), fmaxf(s2, s3)));
    }
#pragma unroll
    for (int o = 16; o; o >>= 1) mx = fmaxf(mx, __shfl_xor_sync(0xffffffffu, mx, o));

    float sum = 0.f;
#pragma unroll
    for (int tt = 0; tt < 4; tt++) {
        float4 s = sc[tt];
        s.x = (s.x < -1.0e38f) ? 0.f : __expf(s.x - mx);
        s.y = (s.y < -1.0e38f) ? 0.f : __expf(s.y - mx);
        s.z = (s.z < -1.0e38f) ? 0.f : __expf(s.z - mx);
        s.w = (s.w < -1.0e38f) ? 0.f : __expf(s.w - mx);
        sc[tt] = s;
        sum += s.x + s.y + s.z + s.w;
    }
#pragma unroll
    for (int o = 16; o; o >>= 1) sum += __shfl_xor_sync(0xffffffffu, sum, o);

    const float* xpT = xpT_g + (size_t)(b * 64 + h * 8) * 512;
    float oa[8] = {0.f, 0.f, 0.f, 0.f, 0.f, 0.f, 0.f, 0.f};
#pragma unroll
    for (int tt = 0; tt < 4; tt++) {
        int q = 4 * lane + 128 * tt;
        float4 s = sc[tt];
#pragma unroll
        for (int f = 0; f < 8; f++) {
            float4 xv = *(const float4*)&xpT[f * 512 + q];   // coalesced over q
            oa[f] += s.x * xv.x + s.y * xv.y + s.z * xv.z + s.w * xv.w;
        }
    }
#pragma unroll
    for (int o = 16; o; o >>= 1) {
#pragma unroll
        for (int f = 0; f < 8; f++) oa[f] += __shfl_xor_sync(0xffffffffu, oa[f], o);
    }

    __shared__ float os[64];
    if (lane == 0) {
        float inv = 1.f / sum;
#pragma unroll
        for (int f = 0; f < 8; f++) {
            float v = oa[f] * inv + x[(size_t)(b * 512 + p) * 64 + h * 8 + f] + bias[h * 8 + f];
            os[h * 8 + f] = (v > 0.f) ? v : expm1f(v);
        }
    }
    __syncthreads();
    if (threadIdx.x < 16)
        ((float4*)(out + (size_t)(b * 512 + p) * 64))[threadIdx.x] =
            ((const float4*)os)[threadIdx.x];
}

// ---------------- launch ----------------
extern "C" void kernel_launch(void* const* d_in, const int* in_sizes, int n_in,
                              void* d_out, int out_size) {
    const float* adj    = (const float*)d_in[0];
    const float* x      = (const float*)d_in[1];
    const float* e      = (const float*)d_in[2];
    const float* W      = (const float*)d_in[3];
    const float* We     = (const float*)d_in[4];
    const float* a_src  = (const float*)d_in[5];
    const float* a_dst  = (const float*)d_in[6];
    const float* a_edge = (const float*)d_in[7];
    const float* bias   = (const float*)d_in[8];

    float* out = (float*)d_out;
    float* e_out = out + Bc * Nc * Cc;   // out first, then e_out

    k_wprep<<<8, 256>>>(We);
    k_proj<<<Bc * Nc, 64>>>(x, W, a_src, a_dst);
    k_edge<<<dim3(Nc / 64, Nc, Bc), 128>>>(e, a_edge, e_out);
    k_attn<<<Bc * Nc, 256>>>(adj, x, bias, out);
}

// round 6
// speedup vs baseline: 2.1576x; 1.2016x over previous
#include <cuda_runtime.h>
#include <cuda_bf16.h>
#include <math.h>

#define Bc 4
#define Nc 512
#define Cc 64
#define Hc 8
#define Fc 8
#define JS 8      // j tiles streamed per block
#define EPD 72    // floats per staged e row (64 data + 8 pad)

typedef unsigned int u32;

// ---------------- scratch (device globals: no allocs allowed) ----------------
__device__ float ssrc_g[Bc * Hc * Nc];             // (b,h,n)
__device__ float sdst_g[Bc * Hc * Nc];             // (b,h,n)
__device__ float xpT_g[Bc * Hc * Fc * Nc];         // projected nodes transposed [b][h][f][q]
__device__ float SE_g[(size_t)Bc * Hc * Nc * Nc];  // edge scores [b][h][p=j][q=i]
// B fragments pre-paired for direct per-thread LDG.64 (L1-resident, 16KB total):
// layout [kk<4][tg<4][n<64][s<2], s=0 -> k2 = kk*8+tg, s=1 -> k2+4
__device__ u32 Bfh_g[4 * 4 * 64 * 2];
__device__ u32 Bfl_g[4 * 4 * 64 * 2];

__device__ __forceinline__ void split2(float2 v, u32& hi, u32& lo) {
    __nv_bfloat16 h0 = __float2bfloat16_rn(v.x), h1 = __float2bfloat16_rn(v.y);
    __nv_bfloat16 l0 = __float2bfloat16_rn(v.x - __bfloat162float(h0));
    __nv_bfloat16 l1 = __float2bfloat16_rn(v.y - __bfloat162float(h1));
    __nv_bfloat162 ph = __halves2bfloat162(h0, h1);
    __nv_bfloat162 pl = __halves2bfloat162(l0, l1);
    hi = *(u32*)&ph;
    lo = *(u32*)&pl;
}

// fast branchless elu: 5-term Taylor on (-0.25,0], __expf-1 below; identity above 0
__device__ __forceinline__ float elu1(float v) {
    float p = fmaf(v, 1.f / 120.f, 1.f / 24.f);
    p = fmaf(p, v, 1.f / 6.f);
    p = fmaf(p, v, 0.5f);
    p = fmaf(p, v, 1.f);
    p = p * v;
    float ex = __expf(v) - 1.f;
    float r = (v > -0.25f) ? p : ex;
    return (v > 0.f) ? v : r;
}

__device__ __forceinline__ u32 smem_u32(const void* p) {
    return (u32)__cvta_generic_to_shared(p);
}

// ---------------- kernel 0: build split-bf16 B fragments ----------------
__global__ void k_wprep(const float* __restrict__ We) {
    int idx = blockIdx.x * 256 + threadIdx.x;      // 0..2047
    int s = idx & 1, n = (idx >> 1) & 63, tg = (idx >> 7) & 3, kk = idx >> 9;
    int k2 = kk * 8 + tg + 4 * s;
    float2 w = make_float2(We[(2 * k2) * 64 + n], We[(2 * k2 + 1) * 64 + n]);
    u32 hi, lo;
    split2(w, hi, lo);
    Bfh_g[idx] = hi;
    Bfl_g[idx] = lo;
}

// ---------------- kernel 1: xp = x@W (transposed out), s_src, s_dst ----------------
__global__ void k_proj(const float* __restrict__ x, const float* __restrict__ W,
                       const float* __restrict__ a_src, const float* __restrict__ a_dst) {
    __shared__ float xs[64];
    __shared__ float xps[64];
    int row = blockIdx.x;                          // b*512 + n
    int t = threadIdx.x;                           // 64 threads
    xs[t] = x[row * 64 + t];
    __syncthreads();
    float acc = 0.f;
#pragma unroll
    for (int c = 0; c < 64; c++) acc = fmaf(xs[c], W[c * 64 + t], acc);
    xps[t] = acc;
    int b = row >> 9, n = row & 511;
    xpT_g[(b * 64 + t) * 512 + n] = acc;           // t = h*8+f
    __syncthreads();
    if (t < 8) {
        float ss = 0.f, sd = 0.f;
#pragma unroll
        for (int f = 0; f < 8; f++) {
            float v = xps[t * 8 + f];
            ss = fmaf(v, a_src[t * 8 + f], ss);
            sd = fmaf(v, a_dst[t * 8 + f], sd);
        }
        ssrc_g[(b * 8 + t) * 512 + n] = ss;
        sdst_g[(b * 8 + t) * 512 + n] = sd;
    }
}

// ---------------- kernel 2: ep = e@We, streamed over j with cp.async double buffer ----
// Block: 128 threads (4 warps, 2x2 M/N). Per iter: one 64(i) x 64(c) raw e tile.
// bf16 hi/lo split happens at fragment-read time (FMA pipe, not MIO).
// Consumed raw buffer doubles as the coalesced-store staging tile (Os).
__global__ void __launch_bounds__(128, 3) k_edge(
    const float* __restrict__ e, const float* __restrict__ a_edge,
    float* __restrict__ e_out) {
    __shared__ __align__(16) float Eb[2][64 * EPD];
    __shared__ float SCs[8 * 64];

    int t = threadIdx.x;
    int i0 = blockIdx.x * 64;
    int j0 = blockIdx.y * JS;
    int b = blockIdx.z;

    int w = t >> 5, lane = t & 31;
    int wm = w & 1, wn2 = w >> 1;
    int g = lane >> 2, tg = lane & 3;

    // B fragments (tiny; L1-hot)
    uint2 BH[4][4], BL[4][4];                      // [kk][ni]
#pragma unroll
    for (int kk = 0; kk < 4; kk++)
#pragma unroll
        for (int ni = 0; ni < 4; ni++) {
            int n = wn2 * 32 + ni * 8 + g;
            int off = (kk * 4 + tg) * 64 + n;
            BH[kk][ni] = ((const uint2*)Bfh_g)[off];
            BL[kk][ni] = ((const uint2*)Bfl_g)[off];
        }

    // per-thread staging coords: 8 float4 per tile
    int sr[8], sc4[8];
    const float* gsrc[8];
#pragma unroll
    for (int u = 0; u < 8; u++) {
        int F = t + 128 * u;
        sr[u] = F >> 4;
        sc4[u] = F & 15;
        gsrc[u] = e + ((size_t)((b * 512 + i0 + sr[u]) * 512 + j0)) * 64 + sc4[u] * 4;
    }

#define CPA(dstp, srcp) \
    asm volatile("cp.async.cg.shared.global [%0], [%1], 16;" \
                 :: "r"(smem_u32(dstp)), "l"(srcp))

    // preload tile 0
#pragma unroll
    for (int u = 0; u < 8; u++)
        CPA(&Eb[0][sr[u] * EPD + sc4[u] * 4], gsrc[u]);
    asm volatile("cp.async.commit_group;");

    for (int jt = 0; jt < JS; jt++) {
        int p = jt & 1;
        int j = j0 + jt;
        // prefetch next tile into other buffer
        if (jt + 1 < JS) {
#pragma unroll
            for (int u = 0; u < 8; u++)
                CPA(&Eb[p ^ 1][sr[u] * EPD + sc4[u] * 4], gsrc[u] + (size_t)(jt + 1) * 64);
        }
        asm volatile("cp.async.commit_group;");
        asm volatile("cp.async.wait_group 1;");
        __syncthreads();

        const float* A = Eb[p];
        float c[2][4][4];
#pragma unroll
        for (int mi = 0; mi < 2; mi++)
#pragma unroll
            for (int ni = 0; ni < 4; ni++)
#pragma unroll
                for (int q = 0; q < 4; q++) c[mi][ni][q] = 0.f;

#pragma unroll
        for (int kk = 0; kk < 4; kk++) {
#pragma unroll
            for (int mi = 0; mi < 2; mi++) {
                int rb = (wm * 32 + mi * 16 + g) * EPD + kk * 16 + 2 * tg;
                float2 e0 = *(const float2*)&A[rb];
                float2 e1 = *(const float2*)&A[rb + 8 * EPD];
                float2 e2 = *(const float2*)&A[rb + 8];
                float2 e3 = *(const float2*)&A[rb + 8 * EPD + 8];
                u32 ah0, ah1, ah2, ah3, al0, al1, al2, al3;
                split2(e0, ah0, al0);
                split2(e1, ah1, al1);
                split2(e2, ah2, al2);
                split2(e3, ah3, al3);
#pragma unroll
                for (int ni = 0; ni < 4; ni++) {
                    float* cc = c[mi][ni];
                    u32 bh0 = BH[kk][ni].x, bh1 = BH[kk][ni].y;
                    u32 bl0 = BL[kk][ni].x, bl1 = BL[kk][ni].y;
#define MMA(A0,A1,A2,A3,B0,B1) \
    asm volatile("mma.sync.aligned.m16n8k16.row.col.f32.bf16.bf16.f32 " \
        "{%0,%1,%2,%3}, {%4,%5,%6,%7}, {%8,%9}, {%0,%1,%2,%3};" \
        : "+f"(cc[0]), "+f"(cc[1]), "+f"(cc[2]), "+f"(cc[3]) \
        : "r"(A0), "r"(A1), "r"(A2), "r"(A3), "r"(B0), "r"(B1))
                    MMA(ah0, ah1, ah2, ah3, bh0, bh1);   // eh * Wh
                    MMA(al0, al1, al2, al3, bh0, bh1);   // el * Wh
                    MMA(ah0, ah1, ah2, ah3, bl0, bl1);   // eh * Wl
#undef MMA
                }
            }
        }
        __syncthreads();   // done reading raw tile; reuse it as Os

        float* Os = Eb[p];
#pragma unroll
        for (int mi = 0; mi < 2; mi++) {
#pragma unroll
            for (int ni = 0; ni < 4; ni++) {
                int h = wn2 * 4 + ni;
                float ae0 = a_edge[h * 8 + 2 * tg];
                float ae1 = a_edge[h * 8 + 2 * tg + 1];
                float c0 = c[mi][ni][0], c1 = c[mi][ni][1];
                float c2 = c[mi][ni][2], c3 = c[mi][ni][3];
                int rAi = wm * 32 + mi * 16 + g, rBi = rAi + 8;
                int col = h * 8 + 2 * tg;
                *(float2*)&Os[rAi * EPD + col] = make_float2(c0, c1);
                *(float2*)&Os[rBi * EPD + col] = make_float2(c2, c3);
                float pA = c0 * ae0 + c1 * ae1;
                float pB = c2 * ae0 + c3 * ae1;
                pA += __shfl_xor_sync(0xffffffffu, pA, 1);
                pA += __shfl_xor_sync(0xffffffffu, pA, 2);
                pB += __shfl_xor_sync(0xffffffffu, pB, 1);
                pB += __shfl_xor_sync(0xffffffffu, pB, 2);
                if (tg == 0) {
                    SCs[h * 64 + rAi] = pA;
                    SCs[h * 64 + rBi] = pB;
                }
            }
        }
        __syncthreads();

        // coalesced stores: e_out (elu on the way out) + SE
        {
            float* eob = e_out + ((size_t)((b * 512 + i0) * 512 + j)) * 64;
#pragma unroll
            for (int u = 0; u < 8; u++) {
                float4 v = *(float4*)&Os[sr[u] * EPD + sc4[u] * 4];
                v.x = elu1(v.x);
                v.y = elu1(v.y);
                v.z = elu1(v.z);
                v.w = elu1(v.w);
                *(float4*)&eob[(size_t)sr[u] * 512 * 64 + sc4[u] * 4] = v;
            }
        }
        {
            int idx = t * 4;                       // 512 floats: [h<8][q<64]
            int h = idx >> 6, q = idx & 63;
            float4 v = *(float4*)&SCs[idx];
            size_t o = ((size_t)((b * 8 + h) * 512 + j)) * 512 + (size_t)(i0 + q);
            *(float4*)&SE_g[o] = v;                // SE[b][h][p=j][q=i]
        }
        __syncthreads();   // protect Os before next prefetch overwrites it
    }
#undef CPA
}

// ---------------- kernel 3: masked softmax + att@xp + residual + elu ----------------
__global__ void __launch_bounds__(256) k_attn(
    const float* __restrict__ adj, const float* __restrict__ x,
    const float* __restrict__ bias, float* __restrict__ out) {
    int bp = blockIdx.x;
    int b = bp >> 9, p = bp & 511;
    int h = threadIdx.x >> 5, lane = threadIdx.x & 31;

    const float* SErow = SE_g + ((size_t)((b * 8 + h) * 512 + p)) * 512;
    const float* adjrow = adj + (size_t)(b * 512 + p) * 512;
    const float* sd = sdst_g + (b * 8 + h) * 512;
    float ssrc = ssrc_g[(b * 8 + h) * 512 + p];

    float4 sc[4];
    float mx = -3.0e38f;
#pragma unroll
    for (int tt = 0; tt < 4; tt++) {
        int q = 4 * lane + 128 * tt;
        float4 a = *(const float4*)&adjrow[q];
        float4 se = *(const float4*)&SErow[q];
        float4 sv = *(const float4*)&sd[q];
        float s0 = ssrc + sv.x + se.x; s0 = (s0 > 0.f) ? s0 : 0.2f * s0; s0 = (a.x < 0.5f) ? -3.0e38f : s0;
        float s1 = ssrc + sv.y + se.y; s1 = (s1 > 0.f) ? s1 : 0.2f * s1; s1 = (a.y < 0.5f) ? -3.0e38f : s1;
        float s2 = ssrc + sv.z + se.z; s2 = (s2 > 0.f) ? s2 : 0.2f * s2; s2 = (a.z < 0.5f) ? -3.0e38f : s2;
        float s3 = ssrc + sv.w + se.w; s3 = (s3 > 0.f) ? s3 : 0.2f * s3; s3 = (a.w < 0.5f) ? -3.0e38f : s3;
        sc[tt] = make_float4(s0, s1, s2, s3);
        mx = fmaxf(mx, fmaxf(fmaxf(s0, s1), fmaxf(s2, s3)));
    }
#pragma unroll
    for (int o = 16; o; o >>= 1) mx = fmaxf(mx, __shfl_xor_sync(0xffffffffu, mx, o));

    float sum = 0.f;
#pragma unroll
    for (int tt = 0; tt < 4; tt++) {
        float4 s = sc[tt];
        s.x = (s.x < -1.0e38f) ? 0.f : __expf(s.x - mx);
        s.y = (s.y < -1.0e38f) ? 0.f : __expf(s.y - mx);
        s.z = (s.z < -1.0e38f) ? 0.f : __expf(s.z - mx);
        s.w = (s.w < -1.0e38f) ? 0.f : __expf(s.w - mx);
        sc[tt] = s;
        sum += s.x + s.y + s.z + s.w;
    }
#pragma unroll
    for (int o = 16; o; o >>= 1) sum += __shfl_xor_sync(0xffffffffu, sum, o);

    const float* xpT = xpT_g + (size_t)(b * 64 + h * 8) * 512;
    float oa[8] = {0.f, 0.f, 0.f, 0.f, 0.f, 0.f, 0.f, 0.f};
#pragma unroll
    for (int tt = 0; tt < 4; tt++) {
        int q = 4 * lane + 128 * tt;
        float4 s = sc[tt];
#pragma unroll
        for (int f = 0; f < 8; f++) {
            float4 xv = *(const float4*)&xpT[f * 512 + q];   // coalesced over q
            oa[f] += s.x * xv.x + s.y * xv.y + s.z * xv.z + s.w * xv.w;
        }
    }
#pragma unroll
    for (int o = 16; o; o >>= 1) {
#pragma unroll
        for (int f = 0; f < 8; f++) oa[f] += __shfl_xor_sync(0xffffffffu, oa[f], o);
    }

    __shared__ float os[64];
    if (lane == 0) {
        float inv = 1.f / sum;
#pragma unroll
        for (int f = 0; f < 8; f++) {
            float v = oa[f] * inv + x[(size_t)(b * 512 + p) * 64 + h * 8 + f] + bias[h * 8 + f];
            os[h * 8 + f] = (v > 0.f) ? v : expm1f(v);
        }
    }
    __syncthreads();
    if (threadIdx.x < 16)
        ((float4*)(out + (size_t)(b * 512 + p) * 64))[threadIdx.x] =
            ((const float4*)os)[threadIdx.x];
}

// ---------------- launch ----------------
extern "C" void kernel_launch(void* const* d_in, const int* in_sizes, int n_in,
                              void* d_out, int out_size) {
    const float* adj    = (const float*)d_in[0];
    const float* x      = (const float*)d_in[1];
    const float* e      = (const float*)d_in[2];
    const float* W      = (const float*)d_in[3];
    const float* We     = (const float*)d_in[4];
    const float* a_src  = (const float*)d_in[5];
    const float* a_dst  = (const float*)d_in[6];
    const float* a_edge = (const float*)d_in[7];
    const float* bias   = (const float*)d_in[8];

    float* out = (float*)d_out;
    float* e_out = out + Bc * Nc * Cc;   // out first, then e_out

    k_wprep<<<8, 256>>>(We);
    k_proj<<<Bc * Nc, 64>>>(x, W, a_src, a_dst);
    k_edge<<<dim3(Nc / 64, Nc / JS, Bc), 128>>>(e, a_edge, e_out);
    k_attn<<<Bc * Nc, 256>>>(adj, x, bias, out);
}

// round 7
// speedup vs baseline: 2.2166x; 1.0274x over previous
#include <cuda_runtime.h>
#include <cuda_bf16.h>
#include <math.h>

#define Bc 4
#define Nc 512
#define Cc 64
#define Hc 8
#define Fc 8
#define JS 8      // j tiles streamed per block
#define EPD 72    // floats per staged e row (64 data + 8 pad)

typedef unsigned int u32;

// ---------------- scratch (device globals: no allocs allowed) ----------------
__device__ float ssrc_g[Bc * Hc * Nc];             // (b,h,n)
__device__ float sdst_g[Bc * Hc * Nc];             // (b,h,n)
__device__ float xpT_g[Bc * Hc * Fc * Nc];         // projected nodes transposed [b][h][f][q]
__device__ float SE_g[(size_t)Bc * Hc * Nc * Nc];  // edge scores [b][h][p=j][q=i]
// B fragments pre-paired for direct per-thread LDG.64 (L1-resident, 16KB total):
// layout [kk<4][tg<4][n<64][s<2], s=0 -> k2 = kk*8+tg, s=1 -> k2+4
__device__ u32 Bfh_g[4 * 4 * 64 * 2];
__device__ u32 Bfl_g[4 * 4 * 64 * 2];

__device__ __forceinline__ void split2(float2 v, u32& hi, u32& lo) {
    __nv_bfloat16 h0 = __float2bfloat16_rn(v.x), h1 = __float2bfloat16_rn(v.y);
    __nv_bfloat16 l0 = __float2bfloat16_rn(v.x - __bfloat162float(h0));
    __nv_bfloat16 l1 = __float2bfloat16_rn(v.y - __bfloat162float(h1));
    __nv_bfloat162 ph = __halves2bfloat162(h0, h1);
    __nv_bfloat162 pl = __halves2bfloat162(l0, l1);
    hi = *(u32*)&ph;
    lo = *(u32*)&pl;
}

// fast branchless elu: 5-term Taylor on (-0.25,0], __expf-1 below; identity above 0
__device__ __forceinline__ float elu1(float v) {
    float p = fmaf(v, 1.f / 120.f, 1.f / 24.f);
    p = fmaf(p, v, 1.f / 6.f);
    p = fmaf(p, v, 0.5f);
    p = fmaf(p, v, 1.f);
    p = p * v;
    float ex = __expf(v) - 1.f;
    float r = (v > -0.25f) ? p : ex;
    return (v > 0.f) ? v : r;
}

__device__ __forceinline__ u32 smem_u32(const void* p) {
    return (u32)__cvta_generic_to_shared(p);
}

// ---------------- kernel 0: build split-bf16 B fragments ----------------
__global__ void k_wprep(const float* __restrict__ We) {
    int idx = blockIdx.x * 256 + threadIdx.x;      // 0..2047
    int s = idx & 1, n = (idx >> 1) & 63, tg = (idx >> 7) & 3, kk = idx >> 9;
    int k2 = kk * 8 + tg + 4 * s;
    float2 w = make_float2(We[(2 * k2) * 64 + n], We[(2 * k2 + 1) * 64 + n]);
    u32 hi, lo;
    split2(w, hi, lo);
    Bfh_g[idx] = hi;
    Bfl_g[idx] = lo;
}

// ---------------- kernel 1: xp = x@W (transposed out), s_src, s_dst ----------------
__global__ void k_proj(const float* __restrict__ x, const float* __restrict__ W,
                       const float* __restrict__ a_src, const float* __restrict__ a_dst) {
    __shared__ float xs[64];
    __shared__ float xps[64];
    int row = blockIdx.x;                          // b*512 + n
    int t = threadIdx.x;                           // 64 threads
    xs[t] = x[row * 64 + t];
    __syncthreads();
    float acc = 0.f;
#pragma unroll
    for (int c = 0; c < 64; c++) acc = fmaf(xs[c], W[c * 64 + t], acc);
    xps[t] = acc;
    int b = row >> 9, n = row & 511;
    xpT_g[(b * 64 + t) * 512 + n] = acc;           // t = h*8+f
    __syncthreads();
    if (t < 8) {
        float ss = 0.f, sd = 0.f;
#pragma unroll
        for (int f = 0; f < 8; f++) {
            float v = xps[t * 8 + f];
            ss = fmaf(v, a_src[t * 8 + f], ss);
            sd = fmaf(v, a_dst[t * 8 + f], sd);
        }
        ssrc_g[(b * 8 + t) * 512 + n] = ss;
        sdst_g[(b * 8 + t) * 512 + n] = sd;
    }
}

// ---------------- kernel 2: ep = e@We, streamed over j, 3-stage cp.async ring ----
// Block: 128 threads (4 warps, 2x2 M/N). Per iter: one 64(i) x 64(c) raw e tile.
// Prefetch depth 2 (wait_group 2) to fully cover DRAM latency.
// Consumed raw buffer doubles as the coalesced-store staging tile (Os).
__global__ void __launch_bounds__(128, 3) k_edge(
    const float* __restrict__ e, const float* __restrict__ a_edge,
    float* __restrict__ e_out) {
    __shared__ __align__(16) float Eb[3][64 * EPD];
    __shared__ float SCs[8 * 64];

    int t = threadIdx.x;
    int i0 = blockIdx.x * 64;
    int j0 = blockIdx.y * JS;
    int b = blockIdx.z;

    int w = t >> 5, lane = t & 31;
    int wm = w & 1, wn2 = w >> 1;
    int g = lane >> 2, tg = lane & 3;

    // B fragments (tiny; L1-hot)
    uint2 BH[4][4], BL[4][4];                      // [kk][ni]
#pragma unroll
    for (int kk = 0; kk < 4; kk++)
#pragma unroll
        for (int ni = 0; ni < 4; ni++) {
            int n = wn2 * 32 + ni * 8 + g;
            int off = (kk * 4 + tg) * 64 + n;
            BH[kk][ni] = ((const uint2*)Bfh_g)[off];
            BL[kk][ni] = ((const uint2*)Bfl_g)[off];
        }

    // per-thread staging coords: 8 float4 per tile
    int sr[8], sc4[8];
    const float* gsrc[8];
#pragma unroll
    for (int u = 0; u < 8; u++) {
        int F = t + 128 * u;
        sr[u] = F >> 4;
        sc4[u] = F & 15;
        gsrc[u] = e + ((size_t)((b * 512 + i0 + sr[u]) * 512 + j0)) * 64 + sc4[u] * 4;
    }

#define CPA(dstp, srcp) \
    asm volatile("cp.async.cg.shared.global [%0], [%1], 16;" \
                 :: "r"(smem_u32(dstp)), "l"(srcp))

    // preload tiles 0 and 1 (one commit group each)
#pragma unroll
    for (int u = 0; u < 8; u++)
        CPA(&Eb[0][sr[u] * EPD + sc4[u] * 4], gsrc[u]);
    asm volatile("cp.async.commit_group;");
#pragma unroll
    for (int u = 0; u < 8; u++)
        CPA(&Eb[1][sr[u] * EPD + sc4[u] * 4], gsrc[u] + 64);
    asm volatile("cp.async.commit_group;");

    for (int jt = 0; jt < JS; jt++) {
        int p = jt % 3;
        int j = j0 + jt;
        // prefetch tile jt+2 into ring slot (jt+2)%3
        if (jt + 2 < JS) {
#pragma unroll
            for (int u = 0; u < 8; u++)
                CPA(&Eb[(jt + 2) % 3][sr[u] * EPD + sc4[u] * 4],
                    gsrc[u] + (size_t)(jt + 2) * 64);
        }
        asm volatile("cp.async.commit_group;");
        asm volatile("cp.async.wait_group 2;");
        __syncthreads();

        const float* A = Eb[p];
        float c[2][4][4];
#pragma unroll
        for (int mi = 0; mi < 2; mi++)
#pragma unroll
            for (int ni = 0; ni < 4; ni++)
#pragma unroll
                for (int q = 0; q < 4; q++) c[mi][ni][q] = 0.f;

#pragma unroll
        for (int kk = 0; kk < 4; kk++) {
#pragma unroll
            for (int mi = 0; mi < 2; mi++) {
                int rb = (wm * 32 + mi * 16 + g) * EPD + kk * 16 + 2 * tg;
                float2 e0 = *(const float2*)&A[rb];
                float2 e1 = *(const float2*)&A[rb + 8 * EPD];
                float2 e2 = *(const float2*)&A[rb + 8];
                float2 e3 = *(const float2*)&A[rb + 8 * EPD + 8];
                u32 ah0, ah1, ah2, ah3, al0, al1, al2, al3;
                split2(e0, ah0, al0);
                split2(e1, ah1, al1);
                split2(e2, ah2, al2);
                split2(e3, ah3, al3);
#pragma unroll
                for (int ni = 0; ni < 4; ni++) {
                    float* cc = c[mi][ni];
                    u32 bh0 = BH[kk][ni].x, bh1 = BH[kk][ni].y;
                    u32 bl0 = BL[kk][ni].x, bl1 = BL[kk][ni].y;
#define MMA(A0,A1,A2,A3,B0,B1) \
    asm volatile("mma.sync.aligned.m16n8k16.row.col.f32.bf16.bf16.f32 " \
        "{%0,%1,%2,%3}, {%4,%5,%6,%7}, {%8,%9}, {%0,%1,%2,%3};" \
        : "+f"(cc[0]), "+f"(cc[1]), "+f"(cc[2]), "+f"(cc[3]) \
        : "r"(A0), "r"(A1), "r"(A2), "r"(A3), "r"(B0), "r"(B1))
                    MMA(ah0, ah1, ah2, ah3, bh0, bh1);   // eh * Wh
                    MMA(al0, al1, al2, al3, bh0, bh1);   // el * Wh
                    MMA(ah0, ah1, ah2, ah3, bl0, bl1);   // eh * Wl
#undef MMA
                }
            }
        }
        __syncthreads();   // done reading raw tile; reuse it as Os

        float* Os = Eb[p];
#pragma unroll
        for (int mi = 0; mi < 2; mi++) {
#pragma unroll
            for (int ni = 0; ni < 4; ni++) {
                int h = wn2 * 4 + ni;
                float ae0 = a_edge[h * 8 + 2 * tg];
                float ae1 = a_edge[h * 8 + 2 * tg + 1];
                float c0 = c[mi][ni][0], c1 = c[mi][ni][1];
                float c2 = c[mi][ni][2], c3 = c[mi][ni][3];
                int rAi = wm * 32 + mi * 16 + g, rBi = rAi + 8;
                int col = h * 8 + 2 * tg;
                *(float2*)&Os[rAi * EPD + col] = make_float2(c0, c1);
                *(float2*)&Os[rBi * EPD + col] = make_float2(c2, c3);
                float pA = c0 * ae0 + c1 * ae1;
                float pB = c2 * ae0 + c3 * ae1;
                pA += __shfl_xor_sync(0xffffffffu, pA, 1);
                pA += __shfl_xor_sync(0xffffffffu, pA, 2);
                pB += __shfl_xor_sync(0xffffffffu, pB, 1);
                pB += __shfl_xor_sync(0xffffffffu, pB, 2);
                if (tg == 0) {
                    SCs[h * 64 + rAi] = pA;
                    SCs[h * 64 + rBi] = pB;
                }
            }
        }
        __syncthreads();

        // coalesced stores: e_out (elu on the way out) + SE
        {
            float* eob = e_out + ((size_t)((b * 512 + i0) * 512 + j)) * 64;
#pragma unroll
            for (int u = 0; u < 8; u++) {
                float4 v = *(float4*)&Os[sr[u] * EPD + sc4[u] * 4];
                v.x = elu1(v.x);
                v.y = elu1(v.y);
                v.z = elu1(v.z);
                v.w = elu1(v.w);
                *(float4*)&eob[(size_t)sr[u] * 512 * 64 + sc4[u] * 4] = v;
            }
        }
        {
            int idx = t * 4;                       // 512 floats: [h<8][q<64]
            int h = idx >> 6, q = idx & 63;
            float4 v = *(float4*)&SCs[idx];
            size_t o = ((size_t)((b * 8 + h) * 512 + j)) * 512 + (size_t)(i0 + q);
            *(float4*)&SE_g[o] = v;                // SE[b][h][p=j][q=i]
        }
        __syncthreads();   // protect Os before next prefetch overwrites it
    }
#undef CPA
}

// ---------------- kernel 3: masked softmax + att@xp + residual + elu ----------------
// Block = (pg, h, b): 8 warps, warp per p = pg*8+wid. xpT slice + sdst row staged
// in smem once per block and shared by all 8 warps (kills the 268MB L2 re-read).
__global__ void __launch_bounds__(256) k_attn(
    const float* __restrict__ adj, const float* __restrict__ x,
    const float* __restrict__ bias, float* __restrict__ out) {
    __shared__ __align__(16) float xs[8 * 512];    // [f][q] 16KB
    __shared__ float sds[512];
    __shared__ float os[8][8];

    int pg = blockIdx.x, h = blockIdx.y, b = blockIdx.z;
    int t = threadIdx.x;
    int wid = t >> 5, lane = t & 31;
    int p = pg * 8 + wid;

    // stage xpT slice (1024 float4) + sdst row (128 float4)
    {
        const float4* src = (const float4*)(xpT_g + (size_t)(b * 64 + h * 8) * 512);
#pragma unroll
        for (int u = 0; u < 4; u++) ((float4*)xs)[t + 256 * u] = src[t + 256 * u];
        if (t < 128)
            ((float4*)sds)[t] = ((const float4*)(sdst_g + (b * 8 + h) * 512))[t];
    }
    __syncthreads();

    const float* SErow = SE_g + ((size_t)((b * 8 + h) * 512 + p)) * 512;
    const float* adjrow = adj + (size_t)(b * 512 + p) * 512;
    float ssrc = ssrc_g[(b * 8 + h) * 512 + p];

    float4 sc[4];
    float mx = -3.0e38f;
#pragma unroll
    for (int tt = 0; tt < 4; tt++) {
        int q = 4 * lane + 128 * tt;
        float4 a = *(const float4*)&adjrow[q];
        float4 se = *(const float4*)&SErow[q];
        float4 sv = *(const float4*)&sds[q];
        float s0 = ssrc + sv.x + se.x; s0 = (s0 > 0.f) ? s0 : 0.2f * s0; s0 = (a.x < 0.5f) ? -3.0e38f : s0;
        float s1 = ssrc + sv.y + se.y; s1 = (s1 > 0.f) ? s1 : 0.2f * s1; s1 = (a.y < 0.5f) ? -3.0e38f : s1;
        float s2 = ssrc + sv.z + se.z; s2 = (s2 > 0.f) ? s2 : 0.2f * s2; s2 = (a.z < 0.5f) ? -3.0e38f : s2;
        float s3 = ssrc + sv.w + se.w; s3 = (s3 > 0.f) ? s3 : 0.2f * s3; s3 = (a.w < 0.5f) ? -3.0e38f : s3;
        sc[tt] = make_float4(s0, s1, s2, s3);
        mx = fmaxf(mx, fmaxf(fmaxf(s0, s1), fmaxf(s2, s3)));
    }
#pragma unroll
    for (int o = 16; o; o >>= 1) mx = fmaxf(mx, __shfl_xor_sync(0xffffffffu, mx, o));

    float sum = 0.f;
#pragma unroll
    for (int tt = 0; tt < 4; tt++) {
        float4 s = sc[tt];
        s.x = (s.x < -1.0e38f) ? 0.f : __expf(s.x - mx);
        s.y = (s.y < -1.0e38f) ? 0.f : __expf(s.y - mx);
        s.z = (s.z < -1.0e38f) ? 0.f : __expf(s.z - mx);
        s.w = (s.w < -1.0e38f) ? 0.f : __expf(s.w - mx);
        sc[tt] = s;
        sum += s.x + s.y + s.z + s.w;
    }
#pragma unroll
    for (int o = 16; o; o >>= 1) sum += __shfl_xor_sync(0xffffffffu, sum, o);

    float oa[8] = {0.f, 0.f, 0.f, 0.f, 0.f, 0.f, 0.f, 0.f};
#pragma unroll
    for (int tt = 0; tt < 4; tt++) {
        int q = 4 * lane + 128 * tt;
        float4 s = sc[tt];
#pragma unroll
        for (int f = 0; f < 8; f++) {
            float4 xv = *(const float4*)&xs[f * 512 + q];    // smem, conflict-free
            oa[f] += s.x * xv.x + s.y * xv.y + s.z * xv.z + s.w * xv.w;
        }
    }
#pragma unroll
    for (int o = 16; o; o >>= 1) {
#pragma unroll
        for (int f = 0; f < 8; f++) oa[f] += __shfl_xor_sync(0xffffffffu, oa[f], o);
    }

    if (lane == 0) {
        float inv = 1.f / sum;
#pragma unroll
        for (int f = 0; f < 8; f++) {
            float v = oa[f] * inv + x[(size_t)(b * 512 + p) * 64 + h * 8 + f] + bias[h * 8 + f];
            os[wid][f] = (v > 0.f) ? v : expm1f(v);
        }
    }
    __syncthreads();
    if (t < 32) {
        int w2 = t >> 2, fi = (t & 3) * 2;
        *(float2*)&out[(size_t)(b * 512 + pg * 8 + w2) * 64 + h * 8 + fi] =
            *(float2*)&os[w2][fi];
    }
}

// ---------------- launch ----------------
extern "C" void kernel_launch(void* const* d_in, const int* in_sizes, int n_in,
                              void* d_out, int out_size) {
    const float* adj    = (const float*)d_in[0];
    const float* x      = (const float*)d_in[1];
    const float* e      = (const float*)d_in[2];
    const float* W      = (const float*)d_in[3];
    const float* We     = (const float*)d_in[4];
    const float* a_src  = (const float*)d_in[5];
    const float* a_dst  = (const float*)d_in[6];
    const float* a_edge = (const float*)d_in[7];
    const float* bias   = (const float*)d_in[8];

    float* out = (float*)d_out;
    float* e_out = out + Bc * Nc * Cc;   // out first, then e_out

    k_wprep<<<8, 256>>>(We);
    k_proj<<<Bc * Nc, 64>>>(x, W, a_src, a_dst);
    k_edge<<<dim3(Nc / 64, Nc / JS, Bc), 128>>>(e, a_edge, e_out);
    k_attn<<<dim3(Nc / 8, Hc, Bc), 256>>>(adj, x, bias, out);
}